// round 5
// baseline (speedup 1.0000x reference)
#include <cuda_runtime.h>
#include <math.h>

#define TILE_E 128
#define K1 67          // 2*IN + 3
#define HID 64
#define INF_DIM 32
#define THREADS 256
#define MAXN 51200

// Scratch aggregation buffer (no cudaMalloc allowed): N*64 order-encoded uints.
__device__ unsigned int g_agg[(size_t)MAXN * HID];

// Order-preserving float<->uint encoding so unsigned atomicMax == float max.
__device__ __forceinline__ unsigned enc_f(float f) {
    unsigned u = __float_as_uint(f);
    return (u & 0x80000000u) ? ~u : (u | 0x80000000u);
}
__device__ __forceinline__ float dec_f(unsigned e) {
    unsigned u = (e & 0x80000000u) ? (e & 0x7FFFFFFFu) : ~e;
    return __uint_as_float(u);
}

__global__ void init_agg_kernel(long long tot) {
    long long i = (long long)blockIdx.x * blockDim.x + threadIdx.x;
    long long stride = (long long)gridDim.x * blockDim.x;
    for (; i < tot; i += stride)
        g_agg[i] = 0x007FFFFFu;   // enc(-inf)
}

// Shared memory layout (in floats):
//  sW1  [67*64]      @ 0
//  sW2  [64*64]      @ 4288
//  sB1  [64]         @ 8384
//  sB2  [64]         @ 8448
//  sT   [67][128]    @ 8512   (tmp transposed: k-major, edge contiguous)
//  sH   [128][68]    @ 17088  (relu(h), row stride 68 to break conflicts)
//  sDst [128] (int)  @ 25792
//  sSrc [128] (int)  @ 25920
// total = 26048 floats = 104192 bytes (dynamic smem)
#define SMEM_FLOATS 26048

__global__ void __launch_bounds__(THREADS, 2)
edge_mlp_kernel(const float* __restrict__ x,
                const int* __restrict__ ei,    // int32: harness canonicalizes int64 -> int32
                const float* __restrict__ ea,
                const float* __restrict__ W1, const float* __restrict__ b1,
                const float* __restrict__ W2, const float* __restrict__ b2,
                long long E, int N)
{
    extern __shared__ float sm[];
    float* sW1 = sm;
    float* sW2 = sm + 4288;
    float* sB1 = sm + 8384;
    float* sB2 = sm + 8448;
    float* sT  = sm + 8512;
    float* sH  = sm + 17088;
    int*   sDst = (int*)(sm + 25792);
    int*   sSrc = (int*)(sm + 25920);

    const int tid = threadIdx.x;

    // Load weights once per (persistent) block.
    for (int i = tid; i < K1 * HID; i += THREADS) sW1[i] = W1[i];
    for (int i = tid; i < HID * HID; i += THREADS) sW2[i] = W2[i];
    if (tid < HID) { sB1[tid] = b1[tid]; sB2[tid] = b2[tid]; }

    const int cg = tid & 15;    // column group: cols c0..c0+3
    const int eg = tid >> 4;    // edge group:   edges e0..e0+7
    const int c0 = cg * 4;
    const int e0 = eg * 8;

    const int ge_part  = tid & (TILE_E - 1);  // gather: which edge
    const int ge_half  = tid >> 7;            // gather: which half of the row

    const long long numTiles = (E + TILE_E - 1) / TILE_E;

    for (long long tile = blockIdx.x; tile < numTiles; tile += gridDim.x) {
        const long long base = tile * (long long)TILE_E;
        __syncthreads();   // previous tile's GEMM2/atomics done with sH/sDst

        // ---- gather indices ----
        {
            if (ge_half == 0) {
                long long g = base + ge_part;
                int s = 0, d = 0;
                if (g < E) {
                    s = ei[g];
                    d = ei[E + g];
                    // defensive clamp: turns a bad dtype assumption into a
                    // rel_err signal instead of an illegal access
                    s = min(max(s, 0), N - 1);
                    d = min(max(d, 0), N - 1);
                }
                sSrc[ge_part] = s; sDst[ge_part] = d;
            }
            __syncthreads();

            const long long g = base + ge_part;
            const float* xi = x + (size_t)sDst[ge_part] * INF_DIM;
            const float* xj = x + (size_t)sSrc[ge_part] * INF_DIM;
            if (ge_half == 0) {
                #pragma unroll
                for (int k = 0; k < INF_DIM; k++)
                    sT[k * TILE_E + ge_part] = xi[k];
            } else {
                #pragma unroll
                for (int k = 0; k < INF_DIM; k++)
                    sT[(INF_DIM + k) * TILE_E + ge_part] = xj[k] - xi[k];
                float a0 = 0.f, a1 = 0.f, a2 = 0.f;
                if (g < E) {
                    a0 = ea[g * 3 + 0]; a1 = ea[g * 3 + 1]; a2 = ea[g * 3 + 2];
                }
                sT[64 * TILE_E + ge_part] = a0;
                sT[65 * TILE_E + ge_part] = a1;
                sT[66 * TILE_E + ge_part] = a2;
            }
        }
        __syncthreads();

        // ---- GEMM1: h = relu(tmp @ W1 + b1), 8 edges x 4 cols per thread ----
        float acc[8][4];
        #pragma unroll
        for (int i = 0; i < 8; i++)
            #pragma unroll
            for (int j = 0; j < 4; j++) acc[i][j] = sB1[c0 + j];

        #pragma unroll 4
        for (int k = 0; k < K1; k++) {
            float4 b  = *(const float4*)&sW1[k * HID + c0];
            float4 a0v = *(const float4*)&sT[k * TILE_E + e0];
            float4 a1v = *(const float4*)&sT[k * TILE_E + e0 + 4];
            float av[8] = {a0v.x, a0v.y, a0v.z, a0v.w, a1v.x, a1v.y, a1v.z, a1v.w};
            #pragma unroll
            for (int i = 0; i < 8; i++) {
                acc[i][0] = fmaf(av[i], b.x, acc[i][0]);
                acc[i][1] = fmaf(av[i], b.y, acc[i][1]);
                acc[i][2] = fmaf(av[i], b.z, acc[i][2]);
                acc[i][3] = fmaf(av[i], b.w, acc[i][3]);
            }
        }
        #pragma unroll
        for (int i = 0; i < 8; i++) {
            float4 v;
            v.x = fmaxf(acc[i][0], 0.f);
            v.y = fmaxf(acc[i][1], 0.f);
            v.z = fmaxf(acc[i][2], 0.f);
            v.w = fmaxf(acc[i][3], 0.f);
            *(float4*)&sH[(e0 + i) * 68 + c0] = v;
        }
        __syncthreads();

        // ---- GEMM2: msg = h @ W2 + b2 ----
        #pragma unroll
        for (int i = 0; i < 8; i++)
            #pragma unroll
            for (int j = 0; j < 4; j++) acc[i][j] = sB2[c0 + j];

        #pragma unroll 4
        for (int k = 0; k < HID; k++) {
            float4 b = *(const float4*)&sW2[k * HID + c0];
            #pragma unroll
            for (int i = 0; i < 8; i++) {
                float a = sH[(e0 + i) * 68 + k];
                acc[i][0] = fmaf(a, b.x, acc[i][0]);
                acc[i][1] = fmaf(a, b.y, acc[i][1]);
                acc[i][2] = fmaf(a, b.z, acc[i][2]);
                acc[i][3] = fmaf(a, b.w, acc[i][3]);
            }
        }

        // ---- scatter: atomic float-max via uint encoding (compiles to RED) ----
        #pragma unroll
        for (int i = 0; i < 8; i++) {
            int e = e0 + i;
            long long g = base + e;
            if (g < E) {
                unsigned* d = g_agg + (size_t)sDst[e] * HID + c0;
                atomicMax(d + 0, enc_f(acc[i][0]));
                atomicMax(d + 1, enc_f(acc[i][1]));
                atomicMax(d + 2, enc_f(acc[i][2]));
                atomicMax(d + 3, enc_f(acc[i][3]));
            }
        }
    }
}

// Output stage: decode agg (empty -> 0), out = sigmoid(agg @ Wo + bo)
__global__ void out_kernel(const float* __restrict__ Wo,
                           const float* __restrict__ bo,
                           float* __restrict__ out, int N)
{
    __shared__ float sWo[64 * 16];
    __shared__ float sBo[16];
    __shared__ float sA[16 * 68];

    const int tid = threadIdx.x;
    for (int i = tid; i < 64 * 16; i += THREADS) sWo[i] = Wo[i];
    if (tid < 16) sBo[tid] = bo[tid];

    const int n0 = blockIdx.x * 16;
    for (int idx = tid; idx < 16 * 64; idx += THREADS) {
        int nl = idx >> 6, k = idx & 63;
        int n = n0 + nl;
        float f = 0.f;
        if (n < N) {
            float v = dec_f(g_agg[(size_t)n * HID + k]);
            f = isfinite(v) ? v : 0.f;   // empty segments -> 0 (PyG fill)
        }
        sA[nl * 68 + k] = f;
    }
    __syncthreads();

    const int nl = tid >> 4, o = tid & 15;
    const int n = n0 + nl;
    if (n < N) {
        float a = sBo[o];
        #pragma unroll
        for (int k = 0; k < 64; k++)
            a = fmaf(sA[nl * 68 + k], sWo[k * 16 + o], a);
        out[(size_t)n * 16 + o] = 1.f / (1.f + expf(-a));
    }
}

extern "C" void kernel_launch(void* const* d_in, const int* in_sizes, int n_in,
                              void* d_out, int out_size)
{
    const float* x  = (const float*)d_in[0];
    const int*   ei = (const int*)d_in[1];     // int64 in reference -> int32 here
    const float* ea = (const float*)d_in[2];
    const float* W1 = (const float*)d_in[3];
    const float* b1 = (const float*)d_in[4];
    const float* W2 = (const float*)d_in[5];
    const float* b2 = (const float*)d_in[6];
    const float* Wo = (const float*)d_in[7];
    const float* bo = (const float*)d_in[8];
    float* out = (float*)d_out;

    const int       N = in_sizes[0] / INF_DIM;
    const long long E = (long long)in_sizes[1] / 2;

    // >48KB dynamic smem opt-in (idempotent; not a stream op, capture-safe)
    cudaFuncSetAttribute(edge_mlp_kernel,
                         cudaFuncAttributeMaxDynamicSharedMemorySize,
                         SMEM_FLOATS * (int)sizeof(float));

    const long long tot = (long long)N * HID;
    int initBlocks = (int)((tot + 256 * 8 - 1) / (256 * 8));
    if (initBlocks > 2048) initBlocks = 2048;
    init_agg_kernel<<<initBlocks, 256>>>(tot);
    edge_mlp_kernel<<<296, THREADS, SMEM_FLOATS * sizeof(float)>>>(
        x, ei, ea, W1, b1, W2, b2, E, N);
    out_kernel<<<(N + 15) / 16, THREADS>>>(Wo, bo, out, N);
}

// round 6
// speedup vs baseline: 1.6577x; 1.6577x over previous
#include <cuda_runtime.h>
#include <math.h>

#define TILE_E 128
#define K1 67          // 2*IN + 3
#define HID 64
#define INF_DIM 32
#define THREADS 256
#define MAXN 51200
#define STR 130        // sT/sHT row stride (even for 8B-aligned LDS.64, conflict-light)

typedef unsigned long long ull;

// ---- packed f32x2 helpers (FFMA2 is PTX-only; ptxas never auto-fuses) ----
__device__ __forceinline__ void ffma2(ull &acc, ull a, ull b) {
    asm("fma.rn.f32x2 %0, %1, %2, %0;" : "+l"(acc) : "l"(a), "l"(b));
}
__device__ __forceinline__ ull dup2(float v) {
    ull r; asm("mov.b64 %0, {%1, %1};" : "=l"(r) : "f"(v)); return r;
}
__device__ __forceinline__ float2 unpk(ull p) {
    float2 f; asm("mov.b64 {%0, %1}, %2;" : "=f"(f.x), "=f"(f.y) : "l"(p)); return f;
}
__device__ __forceinline__ ull pk2(float x, float y) {
    ull r; asm("mov.b64 %0, {%1, %2};" : "=l"(r) : "f"(x), "f"(y)); return r;
}

// Scratch aggregation buffer (no cudaMalloc allowed): N*64 order-encoded uints.
__device__ unsigned int g_agg[(size_t)MAXN * HID];

// Order-preserving float<->uint encoding so unsigned atomicMax == float max.
__device__ __forceinline__ unsigned enc_f(float f) {
    unsigned u = __float_as_uint(f);
    return (u & 0x80000000u) ? ~u : (u | 0x80000000u);
}
__device__ __forceinline__ float dec_f(unsigned e) {
    unsigned u = (e & 0x80000000u) ? (e & 0x7FFFFFFFu) : ~e;
    return __uint_as_float(u);
}

__global__ void init_agg_kernel(long long tot) {
    long long i = (long long)blockIdx.x * blockDim.x + threadIdx.x;
    long long stride = (long long)gridDim.x * blockDim.x;
    for (; i < tot; i += stride)
        g_agg[i] = 0x007FFFFFu;   // enc(-inf)
}

// Shared memory layout (floats):
//  sW1  [67*64]        @ 0
//  sW2  [64*64]        @ 4288
//  sB1  [64]           @ 8384
//  sB2  [64]           @ 8448
//  sT   [67][STR=130]  @ 8512   (tmp transposed: k-major, edges contiguous)
//  sHT  [64][STR=130]  @ 17224  (relu(h) transposed: k-major)
//  sDst [128] (int)    @ 25544
//  sSrc [128] (int)    @ 25672
#define SMEM_FLOATS 25800

__global__ void __launch_bounds__(THREADS, 2)
edge_mlp_kernel(const float* __restrict__ x,
                const int* __restrict__ ei,    // harness canonicalizes int64 -> int32
                const float* __restrict__ ea,
                const float* __restrict__ W1, const float* __restrict__ b1,
                const float* __restrict__ W2, const float* __restrict__ b2,
                long long E, int N)
{
    extern __shared__ float sm[];
    float* sW1 = sm;
    float* sW2 = sm + 4288;
    float* sB1 = sm + 8384;
    float* sB2 = sm + 8448;
    float* sT  = sm + 8512;
    float* sHT = sm + 17224;
    int*   sDst = (int*)(sm + 25544);
    int*   sSrc = (int*)(sm + 25672);

    const int tid = threadIdx.x;

    // Load weights once per (persistent) block.
    for (int i = tid; i < K1 * HID; i += THREADS) sW1[i] = W1[i];
    for (int i = tid; i < HID * HID; i += THREADS) sW2[i] = W2[i];
    if (tid < HID) { sB1[tid] = b1[tid]; sB2[tid] = b2[tid]; }

    const int cg = tid & 15;    // column group: cols c0..c0+3
    const int eg = tid >> 4;    // edge group:   edges e0..e0+7
    const int c0 = cg * 4;
    const int e0 = eg * 8;

    const long long numTiles = (E + TILE_E - 1) / TILE_E;

    for (long long tile = blockIdx.x; tile < numTiles; tile += gridDim.x) {
        const long long base = tile * (long long)TILE_E;
        __syncthreads();   // previous tile fully consumed sT/sHT/sDst

        // ---- indices ----
        if (tid < TILE_E) {
            long long g = base + tid;
            int s = 0, d = 0;
            if (g < E) {
                s = ei[g];
                d = ei[E + g];
                s = min(max(s, 0), N - 1);   // safety clamp
                d = min(max(d, 0), N - 1);
            }
            sSrc[tid] = s; sDst[tid] = d;
        }
        __syncthreads();

        // ---- gather (coalesced): 8 lanes cover one 32-float row via float4 ----
        // task t in [0,1024): e = t>>3, 4-float chunk c4 = (t&7)*4
        #pragma unroll
        for (int it = 0; it < 4; it++) {
            int t  = it * THREADS + tid;
            int e  = t >> 3;
            int c4 = (t & 7) * 4;
            const float4 fi = *(const float4*)&x[(size_t)sDst[e] * INF_DIM + c4];
            const float4 fj = *(const float4*)&x[(size_t)sSrc[e] * INF_DIM + c4];
            sT[(c4 + 0) * STR + e] = fi.x;
            sT[(c4 + 1) * STR + e] = fi.y;
            sT[(c4 + 2) * STR + e] = fi.z;
            sT[(c4 + 3) * STR + e] = fi.w;
            sT[(c4 + 32) * STR + e] = fj.x - fi.x;
            sT[(c4 + 33) * STR + e] = fj.y - fi.y;
            sT[(c4 + 34) * STR + e] = fj.z - fi.z;
            sT[(c4 + 35) * STR + e] = fj.w - fi.w;
        }
        // edge_attr: 384 contiguous floats per tile
        for (int t = tid; t < TILE_E * 3; t += THREADS) {
            int e = t / 3, comp = t - 3 * e;
            float v = (base + e < E) ? ea[base * 3 + t] : 0.f;
            sT[(64 + comp) * STR + e] = v;
        }
        __syncthreads();

        // ---- GEMM1: h = relu(tmp @ W1 + b1) ----
        // acc[p][j]: f32x2 over edge pair (e0+2p, e0+2p+1), col c0+j
        ull acc[4][4];
        {
            ull bi0 = dup2(sB1[c0 + 0]), bi1 = dup2(sB1[c0 + 1]);
            ull bi2 = dup2(sB1[c0 + 2]), bi3 = dup2(sB1[c0 + 3]);
            #pragma unroll
            for (int p = 0; p < 4; p++) {
                acc[p][0] = bi0; acc[p][1] = bi1; acc[p][2] = bi2; acc[p][3] = bi3;
            }
        }
        #pragma unroll 4
        for (int k = 0; k < K1; k++) {
            const float* aT = &sT[k * STR + e0];
            ull a0 = *(const ull*)(aT + 0);
            ull a1 = *(const ull*)(aT + 2);
            ull a2 = *(const ull*)(aT + 4);
            ull a3 = *(const ull*)(aT + 6);
            const float4 bv = *(const float4*)&sW1[k * HID + c0];
            ull b0 = dup2(bv.x), b1v = dup2(bv.y), b2v = dup2(bv.z), b3v = dup2(bv.w);
            ffma2(acc[0][0], a0, b0); ffma2(acc[0][1], a0, b1v); ffma2(acc[0][2], a0, b2v); ffma2(acc[0][3], a0, b3v);
            ffma2(acc[1][0], a1, b0); ffma2(acc[1][1], a1, b1v); ffma2(acc[1][2], a1, b2v); ffma2(acc[1][3], a1, b3v);
            ffma2(acc[2][0], a2, b0); ffma2(acc[2][1], a2, b1v); ffma2(acc[2][2], a2, b2v); ffma2(acc[2][3], a2, b3v);
            ffma2(acc[3][0], a3, b0); ffma2(acc[3][1], a3, b1v); ffma2(acc[3][2], a3, b2v); ffma2(acc[3][3], a3, b3v);
        }
        // relu + store transposed (k-major) for GEMM2
        #pragma unroll
        for (int p = 0; p < 4; p++)
            #pragma unroll
            for (int j = 0; j < 4; j++) {
                float2 v = unpk(acc[p][j]);
                *(ull*)&sHT[(c0 + j) * STR + e0 + 2 * p] =
                    pk2(fmaxf(v.x, 0.f), fmaxf(v.y, 0.f));
            }
        __syncthreads();

        // ---- GEMM2: msg = h @ W2 + b2 ----
        {
            ull bi0 = dup2(sB2[c0 + 0]), bi1 = dup2(sB2[c0 + 1]);
            ull bi2 = dup2(sB2[c0 + 2]), bi3 = dup2(sB2[c0 + 3]);
            #pragma unroll
            for (int p = 0; p < 4; p++) {
                acc[p][0] = bi0; acc[p][1] = bi1; acc[p][2] = bi2; acc[p][3] = bi3;
            }
        }
        #pragma unroll 4
        for (int k = 0; k < HID; k++) {
            const float* aT = &sHT[k * STR + e0];
            ull a0 = *(const ull*)(aT + 0);
            ull a1 = *(const ull*)(aT + 2);
            ull a2 = *(const ull*)(aT + 4);
            ull a3 = *(const ull*)(aT + 6);
            const float4 bv = *(const float4*)&sW2[k * HID + c0];
            ull b0 = dup2(bv.x), b1v = dup2(bv.y), b2v = dup2(bv.z), b3v = dup2(bv.w);
            ffma2(acc[0][0], a0, b0); ffma2(acc[0][1], a0, b1v); ffma2(acc[0][2], a0, b2v); ffma2(acc[0][3], a0, b3v);
            ffma2(acc[1][0], a1, b0); ffma2(acc[1][1], a1, b1v); ffma2(acc[1][2], a1, b2v); ffma2(acc[1][3], a1, b3v);
            ffma2(acc[2][0], a2, b0); ffma2(acc[2][1], a2, b1v); ffma2(acc[2][2], a2, b2v); ffma2(acc[2][3], a2, b3v);
            ffma2(acc[3][0], a3, b0); ffma2(acc[3][1], a3, b1v); ffma2(acc[3][2], a3, b2v); ffma2(acc[3][3], a3, b3v);
        }

        // ---- scatter: atomic float-max via uint encoding (RED.MAX.U32) ----
        #pragma unroll
        for (int p = 0; p < 4; p++) {
            const int eA = e0 + 2 * p;
            float2 v0 = unpk(acc[p][0]), v1 = unpk(acc[p][1]);
            float2 v2 = unpk(acc[p][2]), v3 = unpk(acc[p][3]);
            if (base + eA < E) {
                unsigned* d = g_agg + (size_t)sDst[eA] * HID + c0;
                atomicMax(d + 0, enc_f(v0.x));
                atomicMax(d + 1, enc_f(v1.x));
                atomicMax(d + 2, enc_f(v2.x));
                atomicMax(d + 3, enc_f(v3.x));
            }
            if (base + eA + 1 < E) {
                unsigned* d = g_agg + (size_t)sDst[eA + 1] * HID + c0;
                atomicMax(d + 0, enc_f(v0.y));
                atomicMax(d + 1, enc_f(v1.y));
                atomicMax(d + 2, enc_f(v2.y));
                atomicMax(d + 3, enc_f(v3.y));
            }
        }
    }
}

// Output stage: decode agg (empty -> 0), out = sigmoid(agg @ Wo + bo)
__global__ void out_kernel(const float* __restrict__ Wo,
                           const float* __restrict__ bo,
                           float* __restrict__ out, int N)
{
    __shared__ float sWo[64 * 16];
    __shared__ float sBo[16];
    __shared__ float sA[16 * 68];

    const int tid = threadIdx.x;
    for (int i = tid; i < 64 * 16; i += THREADS) sWo[i] = Wo[i];
    if (tid < 16) sBo[tid] = bo[tid];

    const int n0 = blockIdx.x * 16;
    for (int idx = tid; idx < 16 * 64; idx += THREADS) {
        int nl = idx >> 6, k = idx & 63;
        int n = n0 + nl;
        float f = 0.f;
        if (n < N) {
            float v = dec_f(g_agg[(size_t)n * HID + k]);
            f = isfinite(v) ? v : 0.f;   // empty segments -> 0 (PyG fill)
        }
        sA[nl * 68 + k] = f;
    }
    __syncthreads();

    const int nl = tid >> 4, o = tid & 15;
    const int n = n0 + nl;
    if (n < N) {
        float a = sBo[o];
        #pragma unroll
        for (int k = 0; k < 64; k++)
            a = fmaf(sA[nl * 68 + k], sWo[k * 16 + o], a);
        out[(size_t)n * 16 + o] = 1.f / (1.f + expf(-a));
    }
}

extern "C" void kernel_launch(void* const* d_in, const int* in_sizes, int n_in,
                              void* d_out, int out_size)
{
    const float* x  = (const float*)d_in[0];
    const int*   ei = (const int*)d_in[1];     // int64 in reference -> int32 here
    const float* ea = (const float*)d_in[2];
    const float* W1 = (const float*)d_in[3];
    const float* b1 = (const float*)d_in[4];
    const float* W2 = (const float*)d_in[5];
    const float* b2 = (const float*)d_in[6];
    const float* Wo = (const float*)d_in[7];
    const float* bo = (const float*)d_in[8];
    float* out = (float*)d_out;

    const int       N = in_sizes[0] / INF_DIM;
    const long long E = (long long)in_sizes[1] / 2;

    cudaFuncSetAttribute(edge_mlp_kernel,
                         cudaFuncAttributeMaxDynamicSharedMemorySize,
                         SMEM_FLOATS * (int)sizeof(float));

    const long long tot = (long long)N * HID;
    int initBlocks = (int)((tot + 256 * 8 - 1) / (256 * 8));
    if (initBlocks > 2048) initBlocks = 2048;
    init_agg_kernel<<<initBlocks, 256>>>(tot);
    edge_mlp_kernel<<<296, THREADS, SMEM_FLOATS * sizeof(float)>>>(
        x, ei, ea, W1, b1, W2, b2, E, N);
    out_kernel<<<(N + 15) / 16, THREADS>>>(Wo, bo, out, N);
}